// round 6
// baseline (speedup 1.0000x reference)
#include <cuda_runtime.h>
#include <cuda_bf16.h>
#include <cstdint>
#include <math.h>

#define N_TOT    8192
#define B_HALF   4096
#define D_DIM    256
#define NBLOCKS  64          // 8192 / 128 row/col blocks
#define NTILE    2080        // 64*65/2 upper-triangle tiles
#define GRID_MAIN 148

#define KS_B    528          // smem row stride bytes (33*16, conflict-free ldmatrix)
#define TILE_B  (128 * KS_B) // 67584 per 128-row tile
#define SMEM_TOTAL (3 * TILE_B)   // A + 2x B = 202752

// Scratch (__device__ globals; every value read is rewritten each run)
__device__ __nv_bfloat16 g_znb[(size_t)N_TOT * D_DIM];
__device__ float g_rowpart[NBLOCKS][NBLOCKS][128];   // [mt][nt] valid for nt>=mt
__device__ float g_colpart[NBLOCKS][NBLOCKS][128];   // [nt][mt] valid for mt<nt
__device__ float g_pos[N_TOT];
__device__ float g_finpart[NBLOCKS];
__device__ unsigned g_count = 0;     // barrier arrive counter (returns to 0)
__device__ unsigned g_gen   = 0;     // barrier generation (monotonic, wrap-safe)

// ---------------------------------------------------------------------------
__device__ __forceinline__ uint32_t smem_u32(const void* p) {
    uint32_t a;
    asm("{ .reg .u64 t; cvta.to.shared.u64 t, %1; cvt.u32.u64 %0, t; }" : "=r"(a) : "l"(p));
    return a;
}
#define CP_ASYNC16(dst, src) \
    asm volatile("cp.async.cg.shared.global [%0], [%1], 16;" :: "r"(dst), "l"(src))
#define CP_COMMIT() asm volatile("cp.async.commit_group;" ::: "memory")
#define CP_WAIT0()  asm volatile("cp.async.wait_group 0;" ::: "memory")

#define LDSM4(r, addr) \
    asm volatile("ldmatrix.sync.aligned.m8n8.x4.shared.b16 {%0,%1,%2,%3}, [%4];" \
        : "=r"((r)[0]), "=r"((r)[1]), "=r"((r)[2]), "=r"((r)[3]) : "r"(addr))

#define MMA16816(c, a, b0, b1) \
    asm volatile("mma.sync.aligned.m16n8k16.row.col.f32.bf16.bf16.f32 " \
        "{%0,%1,%2,%3}, {%4,%5,%6,%7}, {%8,%9}, {%0,%1,%2,%3};" \
        : "+f"((c)[0]), "+f"((c)[1]), "+f"((c)[2]), "+f"((c)[3]) \
        : "r"((a)[0]), "r"((a)[1]), "r"((a)[2]), "r"((a)[3]), "r"(b0), "r"(b1))

// Sense-reversing grid barrier (all 148 CTAs co-resident: smem forces occ=1,
// grid <= SM count). Cooperative-groups grid.sync pattern.
__device__ __forceinline__ void grid_barrier(unsigned& mygen) {
    __syncthreads();
    if (threadIdx.x == 0) {
        __threadfence();
        unsigned prev = atomicAdd(&g_count, 1u);
        if (prev == GRID_MAIN - 1) {
            g_count = 0;
            __threadfence();
            atomicAdd(&g_gen, 1u);
        } else {
            while (*(volatile unsigned*)&g_gen == mygen) { }
        }
        __threadfence();
    }
    __syncthreads();
    mygen++;
}

// ---------------------------------------------------------------------------
// ONE persistent kernel: norm -> barrier -> triangle GEMM -> barrier ->
// block-finish -> barrier -> CTA0 final sum. Deterministic throughout.
// ---------------------------------------------------------------------------
__global__ void __launch_bounds__(256, 1) ntxent_mega(
        const float* __restrict__ zi, const float* __restrict__ zj,
        float* __restrict__ out) {
    extern __shared__ char smem[];
    __shared__ float red_r[4][128];
    __shared__ float red_c[2][128];

    const int tid = threadIdx.x, lane = tid & 31, w = tid >> 5;
    unsigned mygen = 0;

    // ================= Phase 1: normalize (warp per row) =================
    for (int row = blockIdx.x * 8 + w; row < N_TOT; row += GRID_MAIN * 8) {
        const float4* src = (row < B_HALF)
            ? (const float4*)(zi + (size_t)row * D_DIM)
            : (const float4*)(zj + (size_t)(row - B_HALF) * D_DIM);
        float4 a = src[lane];
        float4 b = src[lane + 32];
        float s = a.x * a.x + a.y * a.y + a.z * a.z + a.w * a.w
                + b.x * b.x + b.y * b.y + b.z * b.z + b.w * b.w;
        #pragma unroll
        for (int o = 16; o > 0; o >>= 1) s += __shfl_xor_sync(0xffffffffu, s, o);
        float scale = 1.41421356237309515f / fmaxf(sqrtf(s), 1e-8f);

        __nv_bfloat16* dst = g_znb + (size_t)row * D_DIM;
        __nv_bfloat162 p0 = __floats2bfloat162_rn(a.x * scale, a.y * scale);
        __nv_bfloat162 p1 = __floats2bfloat162_rn(a.z * scale, a.w * scale);
        __nv_bfloat162 p2 = __floats2bfloat162_rn(b.x * scale, b.y * scale);
        __nv_bfloat162 p3 = __floats2bfloat162_rn(b.z * scale, b.w * scale);
        uint2 u0, u1;
        u0.x = *(uint32_t*)&p0; u0.y = *(uint32_t*)&p1;
        u1.x = *(uint32_t*)&p2; u1.y = *(uint32_t*)&p3;
        *(uint2*)(dst + lane * 4)       = u0;
        *(uint2*)(dst + 128 + lane * 4) = u1;
    }

    grid_barrier(mygen);

    // ================= Phase 2: upper-triangle fused GEMM =================
    {
        const int wm = w >> 2, wn = w & 3;
        const int warpM0 = wm * 64, warpN0 = wn * 32;
        const int g = lane >> 2, tig = lane & 3;

        const uint32_t sbase = smem_u32(smem);
        const uint32_t sA = sbase;
        const uint32_t sBb = sbase + TILE_B;

        const int t0 = (blockIdx.x * NTILE) / GRID_MAIN;
        const int t1 = ((blockIdx.x + 1) * NTILE) / GRID_MAIN;

        int mt = 0, rem = t0;
        while (rem >= NBLOCKS - mt) { rem -= NBLOCKS - mt; mt++; }
        int nt = mt + rem;

        // prologue: A(mt) and B(nt) into buf0
        {
            const char* gA = (const char*)(g_znb + (size_t)mt * 128 * D_DIM);
            const char* gB = (const char*)(g_znb + (size_t)nt * 128 * D_DIM);
            #pragma unroll
            for (int it = 0; it < 16; it++) {
                int flat = it * 256 + tid;
                int r = flat >> 5, q = flat & 31;
                CP_ASYNC16(sA + r * KS_B + q * 16, gA + r * 512 + q * 16);
                CP_ASYNC16(sBb + r * KS_B + q * 16, gB + r * 512 + q * 16);
            }
        }
        CP_COMMIT();
        CP_WAIT0();
        __syncthreads();

        int cur_mt = mt;
        for (int t = t0; t < t1; t++) {
            const int buf = (t - t0) & 1;
            const bool have_next = (t + 1 < t1);
            int nmt = mt, nnt = nt + 1;
            if (nnt == NBLOCKS) { nmt = mt + 1; nnt = nmt; }

            if (have_next) {
                const uint32_t sBn = sBb + (buf ^ 1) * TILE_B;
                const char* gB = (const char*)(g_znb + (size_t)nnt * 128 * D_DIM);
                #pragma unroll
                for (int it = 0; it < 16; it++) {
                    int flat = it * 256 + tid;
                    int r = flat >> 5, q = flat & 31;
                    CP_ASYNC16(sBn + r * KS_B + q * 16, gB + r * 512 + q * 16);
                }
            }
            CP_COMMIT();

            const uint32_t sB = sBb + buf * TILE_B;
            float acc[4][4][4];
            #pragma unroll
            for (int mf = 0; mf < 4; mf++)
                #pragma unroll
                for (int nf = 0; nf < 4; nf++)
                    #pragma unroll
                    for (int e = 0; e < 4; e++) acc[mf][nf][e] = 0.f;

            #pragma unroll 4
            for (int kk = 0; kk < 16; kk++) {
                const int kb = kk * 32;
                uint32_t af[4][4], bf[2][4];
                #pragma unroll
                for (int mf = 0; mf < 4; mf++) {
                    uint32_t addr = sA + (warpM0 + mf * 16 + (lane & 15)) * KS_B
                                  + kb + ((lane >> 4) & 1) * 16;
                    LDSM4(af[mf], addr);
                }
                #pragma unroll
                for (int p = 0; p < 2; p++) {
                    uint32_t addr = sB + (warpN0 + p * 16 + ((lane & 16) >> 1) + (lane & 7)) * KS_B
                                  + kb + ((lane >> 3) & 1) * 16;
                    LDSM4(bf[p], addr);
                }
                #pragma unroll
                for (int mf = 0; mf < 4; mf++)
                    #pragma unroll
                    for (int nf = 0; nf < 4; nf++)
                        MMA16816(acc[mf][nf], af[mf], bf[nf >> 1][(nf & 1) * 2],
                                 bf[nf >> 1][(nf & 1) * 2 + 1]);
            }

            const bool is_diag = (mt == nt);
            const bool is_pos  = (nt == mt + 32);
            const int  m0 = mt * 128;

            float rowsum[8], colsum[8];
            #pragma unroll
            for (int s = 0; s < 8; s++) { rowsum[s] = 0.f; colsum[s] = 0.f; }

            #pragma unroll
            for (int mf = 0; mf < 4; mf++)
                #pragma unroll
                for (int nf = 0; nf < 4; nf++)
                    #pragma unroll
                    for (int e = 0; e < 4; e++) {
                        float l = acc[mf][nf][e];
                        float ex = __expf(l);
                        int lr = warpM0 + mf * 16 + g + (e >> 1) * 8;
                        int lc = warpN0 + nf * 8 + tig * 2 + (e & 1);
                        if (lr == lc) {
                            if (is_diag) ex = 0.f;
                            if (is_pos) {
                                g_pos[m0 + lr] = l;
                                g_pos[m0 + lr + B_HALF] = l;
                            }
                        }
                        rowsum[mf * 2 + (e >> 1)] += ex;
                        colsum[nf * 2 + (e & 1)]  += ex;
                    }

            #pragma unroll
            for (int s = 0; s < 8; s++) {
                rowsum[s] += __shfl_xor_sync(0xffffffffu, rowsum[s], 1);
                rowsum[s] += __shfl_xor_sync(0xffffffffu, rowsum[s], 2);
            }
            #pragma unroll
            for (int s = 0; s < 8; s++) {
                colsum[s] += __shfl_xor_sync(0xffffffffu, colsum[s], 4);
                colsum[s] += __shfl_xor_sync(0xffffffffu, colsum[s], 8);
                colsum[s] += __shfl_xor_sync(0xffffffffu, colsum[s], 16);
            }
            if (tig == 0) {
                #pragma unroll
                for (int mf = 0; mf < 4; mf++) {
                    red_r[wn][warpM0 + mf * 16 + g]     = rowsum[mf * 2 + 0];
                    red_r[wn][warpM0 + mf * 16 + g + 8] = rowsum[mf * 2 + 1];
                }
            }
            if (g == 0) {
                #pragma unroll
                for (int nf = 0; nf < 4; nf++) {
                    red_c[wm][warpN0 + nf * 8 + tig * 2]     = colsum[nf * 2 + 0];
                    red_c[wm][warpN0 + nf * 8 + tig * 2 + 1] = colsum[nf * 2 + 1];
                }
            }
            __syncthreads();
            if (tid < 128) {
                float rp = (red_r[0][tid] + red_r[1][tid]) + (red_r[2][tid] + red_r[3][tid]);
                g_rowpart[mt][nt][tid] = rp;
                if (!is_diag) g_colpart[nt][mt][tid] = red_c[0][tid] + red_c[1][tid];
            }

            CP_WAIT0();
            __syncthreads();

            if (have_next && nmt != cur_mt) {
                const char* gA = (const char*)(g_znb + (size_t)nmt * 128 * D_DIM);
                #pragma unroll
                for (int it = 0; it < 16; it++) {
                    int flat = it * 256 + tid;
                    int r = flat >> 5, q = flat & 31;
                    CP_ASYNC16(sA + r * KS_B + q * 16, gA + r * 512 + q * 16);
                }
                CP_COMMIT();
                CP_WAIT0();
                __syncthreads();
                cur_mt = nmt;
            }
            mt = nmt; nt = nnt;
        }
    }

    grid_barrier(mygen);

    // ============ Phase 3: per-block logsumexp assembly (64 CTAs) ============
    if (blockIdx.x < NBLOCKS && tid < 128) {
        const int r = blockIdx.x;
        float tot = 0.f;
        for (int nt = r; nt < NBLOCKS; nt++) tot += g_rowpart[r][nt][tid];
        for (int m = 0; m < r; m++)          tot += g_colpart[r][m][tid];
        float v = logf(tot) - g_pos[r * 128 + tid];
        #pragma unroll
        for (int o = 16; o > 0; o >>= 1) v += __shfl_xor_sync(0xffffffffu, v, o);
        // combine the 4 warps via red_r row 0 (smem reused; safe post-barrier)
        if ((tid & 31) == 0) red_r[0][tid >> 5] = v;
        __syncwarp();
    }
    __syncthreads();
    if (blockIdx.x < NBLOCKS && tid == 0) {
        g_finpart[blockIdx.x] = (red_r[0][0] + red_r[0][1]) + (red_r[0][2] + red_r[0][3]);
    }

    grid_barrier(mygen);

    // ================= Phase 4: final mean (CTA 0) =================
    if (blockIdx.x == 0 && tid < 64) {
        float s = g_finpart[tid];
        #pragma unroll
        for (int o = 16; o > 0; o >>= 1) s += __shfl_xor_sync(0xffffffffu, s, o);
        if ((tid & 31) == 0) red_c[0][tid >> 5] = s;
        __syncwarp();
        if (tid == 0) out[0] = (red_c[0][0] + red_c[0][1]) * (1.0f / (float)N_TOT);
    }
}

// ---------------------------------------------------------------------------
extern "C" void kernel_launch(void* const* d_in, const int* in_sizes, int n_in,
                              void* d_out, int out_size) {
    const float* zi = (const float*)d_in[0];
    const float* zj = (const float*)d_in[1];
    float* out = (float*)d_out;

    cudaFuncSetAttribute(ntxent_mega, cudaFuncAttributeMaxDynamicSharedMemorySize,
                         SMEM_TOTAL);

    ntxent_mega<<<GRID_MAIN, 256, SMEM_TOTAL>>>(zi, zj, out);
}

// round 7
// speedup vs baseline: 1.0272x; 1.0272x over previous
#include <cuda_runtime.h>
#include <cuda_bf16.h>
#include <cstdint>
#include <math.h>

#define N_TOT    8192
#define B_HALF   4096
#define D_DIM    256
#define NBLOCKS  64          // 8192 / 128 row/col blocks
#define NTILE    2080        // 64*65/2 upper-triangle tiles
#define GRID_MAIN 148
#define NTHREADS 512

#define KS_B    528          // smem row stride bytes (33*16, conflict-free ldmatrix)
#define TILE_B  (128 * KS_B) // 67584 per 128-row tile
#define SMEM_TOTAL (3 * TILE_B)   // A + 2x B = 202752

// Scratch (__device__ globals; every value read is rewritten each run)
__device__ __nv_bfloat16 g_znb[(size_t)N_TOT * D_DIM];
__device__ float g_rowpart[NBLOCKS][NBLOCKS][128];   // [mt][nt] valid for nt>=mt
__device__ float g_colpart[NBLOCKS][NBLOCKS][128];   // [nt][mt] valid for mt<nt
__device__ float g_pos[N_TOT];
__device__ float g_finpart[NBLOCKS];
__device__ unsigned g_count = 0;
__device__ unsigned g_gen   = 0;

// ---------------------------------------------------------------------------
__device__ __forceinline__ uint32_t smem_u32(const void* p) {
    uint32_t a;
    asm("{ .reg .u64 t; cvta.to.shared.u64 t, %1; cvt.u32.u64 %0, t; }" : "=r"(a) : "l"(p));
    return a;
}
#define CP_ASYNC16(dst, src) \
    asm volatile("cp.async.cg.shared.global [%0], [%1], 16;" :: "r"(dst), "l"(src))
#define CP_COMMIT() asm volatile("cp.async.commit_group;" ::: "memory")
#define CP_WAIT0()  asm volatile("cp.async.wait_group 0;" ::: "memory")

#define LDSM4(r, addr) \
    asm volatile("ldmatrix.sync.aligned.m8n8.x4.shared.b16 {%0,%1,%2,%3}, [%4];" \
        : "=r"((r)[0]), "=r"((r)[1]), "=r"((r)[2]), "=r"((r)[3]) : "r"(addr))

#define MMA16816(c, a, b0, b1) \
    asm volatile("mma.sync.aligned.m16n8k16.row.col.f32.bf16.bf16.f32 " \
        "{%0,%1,%2,%3}, {%4,%5,%6,%7}, {%8,%9}, {%0,%1,%2,%3};" \
        : "+f"((c)[0]), "+f"((c)[1]), "+f"((c)[2]), "+f"((c)[3]) \
        : "r"((a)[0]), "r"((a)[1]), "r"((a)[2]), "r"((a)[3]), "r"(b0), "r"(b1))

// Sense-reversing grid barrier (all 148 CTAs co-resident: smem forces occ=1).
__device__ __forceinline__ void grid_barrier(unsigned& mygen) {
    __syncthreads();
    if (threadIdx.x == 0) {
        __threadfence();
        unsigned prev = atomicAdd(&g_count, 1u);
        if (prev == GRID_MAIN - 1) {
            g_count = 0;
            __threadfence();
            atomicAdd(&g_gen, 1u);
        } else {
            while (*(volatile unsigned*)&g_gen == mygen) { }
        }
        __threadfence();
    }
    __syncthreads();
    mygen++;
}

// ---------------------------------------------------------------------------
// Persistent kernel, 512 threads: norm -> barrier -> triangle GEMM (16 warps,
// 4x4 warp grid, 32x32 warp tiles) -> barrier -> finish -> barrier -> CTA0.
// ---------------------------------------------------------------------------
__global__ void __launch_bounds__(NTHREADS, 1) ntxent_mega(
        const float* __restrict__ zi, const float* __restrict__ zj,
        float* __restrict__ out) {
    extern __shared__ char smem[];
    __shared__ float red_r[4][128];
    __shared__ float red_c[4][128];

    const int tid = threadIdx.x, lane = tid & 31, w = tid >> 5;
    unsigned mygen = 0;

    // ================= Phase 1: normalize (warp per row) =================
    for (int row = blockIdx.x * 16 + w; row < N_TOT; row += GRID_MAIN * 16) {
        const float4* src = (row < B_HALF)
            ? (const float4*)(zi + (size_t)row * D_DIM)
            : (const float4*)(zj + (size_t)(row - B_HALF) * D_DIM);
        float4 a = src[lane];
        float4 b = src[lane + 32];
        float s = a.x * a.x + a.y * a.y + a.z * a.z + a.w * a.w
                + b.x * b.x + b.y * b.y + b.z * b.z + b.w * b.w;
        #pragma unroll
        for (int o = 16; o > 0; o >>= 1) s += __shfl_xor_sync(0xffffffffu, s, o);
        float scale = 1.41421356237309515f / fmaxf(sqrtf(s), 1e-8f);

        __nv_bfloat16* dst = g_znb + (size_t)row * D_DIM;
        __nv_bfloat162 p0 = __floats2bfloat162_rn(a.x * scale, a.y * scale);
        __nv_bfloat162 p1 = __floats2bfloat162_rn(a.z * scale, a.w * scale);
        __nv_bfloat162 p2 = __floats2bfloat162_rn(b.x * scale, b.y * scale);
        __nv_bfloat162 p3 = __floats2bfloat162_rn(b.z * scale, b.w * scale);
        uint2 u0, u1;
        u0.x = *(uint32_t*)&p0; u0.y = *(uint32_t*)&p1;
        u1.x = *(uint32_t*)&p2; u1.y = *(uint32_t*)&p3;
        *(uint2*)(dst + lane * 4)       = u0;
        *(uint2*)(dst + 128 + lane * 4) = u1;
    }

    grid_barrier(mygen);

    // ================= Phase 2: upper-triangle fused GEMM =================
    {
        const int wm = w >> 2, wn = w & 3;                 // 4x4 warp grid
        const int warpM0 = wm * 32, warpN0 = wn * 32;      // 32x32 warp tile
        const int g = lane >> 2, tig = lane & 3;

        const uint32_t sbase = smem_u32(smem);
        const uint32_t sA = sbase;
        const uint32_t sBb = sbase + TILE_B;

        const int t0 = (blockIdx.x * NTILE) / GRID_MAIN;
        const int t1 = ((blockIdx.x + 1) * NTILE) / GRID_MAIN;

        int mt = 0, rem = t0;
        while (rem >= NBLOCKS - mt) { rem -= NBLOCKS - mt; mt++; }
        int nt = mt + rem;

        // prologue: A(mt) and B(nt) into buf0
        {
            const char* gA = (const char*)(g_znb + (size_t)mt * 128 * D_DIM);
            const char* gB = (const char*)(g_znb + (size_t)nt * 128 * D_DIM);
            #pragma unroll
            for (int it = 0; it < 8; it++) {
                int flat = it * NTHREADS + tid;
                int r = flat >> 5, q = flat & 31;
                CP_ASYNC16(sA + r * KS_B + q * 16, gA + r * 512 + q * 16);
                CP_ASYNC16(sBb + r * KS_B + q * 16, gB + r * 512 + q * 16);
            }
        }
        CP_COMMIT();
        CP_WAIT0();
        __syncthreads();

        int cur_mt = mt;
        for (int t = t0; t < t1; t++) {
            const int buf = (t - t0) & 1;
            const bool have_next = (t + 1 < t1);
            int nmt = mt, nnt = nt + 1;
            if (nnt == NBLOCKS) { nmt = mt + 1; nnt = nmt; }

            if (have_next) {   // prefetch next tile's B into the other buffer
                const uint32_t sBn = sBb + (buf ^ 1) * TILE_B;
                const char* gB = (const char*)(g_znb + (size_t)nnt * 128 * D_DIM);
                #pragma unroll
                for (int it = 0; it < 8; it++) {
                    int flat = it * NTHREADS + tid;
                    int r = flat >> 5, q = flat & 31;
                    CP_ASYNC16(sBn + r * KS_B + q * 16, gB + r * 512 + q * 16);
                }
            }
            CP_COMMIT();

            // ---- 128x128x256 tile GEMM, 32x32 per warp ----
            const uint32_t sB = sBb + buf * TILE_B;
            float acc[2][4][4];
            #pragma unroll
            for (int mf = 0; mf < 2; mf++)
                #pragma unroll
                for (int nf = 0; nf < 4; nf++)
                    #pragma unroll
                    for (int e = 0; e < 4; e++) acc[mf][nf][e] = 0.f;

            #pragma unroll 4
            for (int kk = 0; kk < 16; kk++) {
                const int kb = kk * 32;
                uint32_t af[2][4], bf[2][4];
                #pragma unroll
                for (int mf = 0; mf < 2; mf++) {
                    uint32_t addr = sA + (warpM0 + mf * 16 + (lane & 15)) * KS_B
                                  + kb + ((lane >> 4) & 1) * 16;
                    LDSM4(af[mf], addr);
                }
                #pragma unroll
                for (int p = 0; p < 2; p++) {
                    uint32_t addr = sB + (warpN0 + p * 16 + ((lane & 16) >> 1) + (lane & 7)) * KS_B
                                  + kb + ((lane >> 3) & 1) * 16;
                    LDSM4(bf[p], addr);
                }
                #pragma unroll
                for (int mf = 0; mf < 2; mf++)
                    #pragma unroll
                    for (int nf = 0; nf < 4; nf++)
                        MMA16816(acc[mf][nf], af[mf], bf[nf >> 1][(nf & 1) * 2],
                                 bf[nf >> 1][(nf & 1) * 2 + 1]);
            }

            // ---- epilogue: exp, row + col sums, diag/positive ----
            const bool is_diag = (mt == nt);
            const bool is_pos  = (nt == mt + 32);
            const int  m0 = mt * 128;

            float rowsum[4], colsum[8];
            #pragma unroll
            for (int s = 0; s < 4; s++) rowsum[s] = 0.f;
            #pragma unroll
            for (int s = 0; s < 8; s++) colsum[s] = 0.f;

            #pragma unroll
            for (int mf = 0; mf < 2; mf++)
                #pragma unroll
                for (int nf = 0; nf < 4; nf++)
                    #pragma unroll
                    for (int e = 0; e < 4; e++) {
                        float l = acc[mf][nf][e];
                        float ex = __expf(l);
                        int lr = warpM0 + mf * 16 + g + (e >> 1) * 8;
                        int lc = warpN0 + nf * 8 + tig * 2 + (e & 1);
                        if (lr == lc) {
                            if (is_diag) ex = 0.f;
                            if (is_pos) {
                                g_pos[m0 + lr] = l;
                                g_pos[m0 + lr + B_HALF] = l;
                            }
                        }
                        rowsum[mf * 2 + (e >> 1)] += ex;
                        colsum[nf * 2 + (e & 1)]  += ex;
                    }

            #pragma unroll
            for (int s = 0; s < 4; s++) {
                rowsum[s] += __shfl_xor_sync(0xffffffffu, rowsum[s], 1);
                rowsum[s] += __shfl_xor_sync(0xffffffffu, rowsum[s], 2);
            }
            #pragma unroll
            for (int s = 0; s < 8; s++) {
                colsum[s] += __shfl_xor_sync(0xffffffffu, colsum[s], 4);
                colsum[s] += __shfl_xor_sync(0xffffffffu, colsum[s], 8);
                colsum[s] += __shfl_xor_sync(0xffffffffu, colsum[s], 16);
            }
            if (tig == 0) {
                #pragma unroll
                for (int mf = 0; mf < 2; mf++) {
                    red_r[wn][warpM0 + mf * 16 + g]     = rowsum[mf * 2 + 0];
                    red_r[wn][warpM0 + mf * 16 + g + 8] = rowsum[mf * 2 + 1];
                }
            }
            if (g == 0) {
                #pragma unroll
                for (int nf = 0; nf < 4; nf++) {
                    red_c[wm][warpN0 + nf * 8 + tig * 2]     = colsum[nf * 2 + 0];
                    red_c[wm][warpN0 + nf * 8 + tig * 2 + 1] = colsum[nf * 2 + 1];
                }
            }
            __syncthreads();
            if (tid < 128) {
                float rp = (red_r[0][tid] + red_r[1][tid]) + (red_r[2][tid] + red_r[3][tid]);
                g_rowpart[mt][nt][tid] = rp;
                if (!is_diag)
                    g_colpart[nt][mt][tid] =
                        (red_c[0][tid] + red_c[1][tid]) + (red_c[2][tid] + red_c[3][tid]);
            }

            CP_WAIT0();
            __syncthreads();

            if (have_next && nmt != cur_mt) {   // A reload on row change
                const char* gA = (const char*)(g_znb + (size_t)nmt * 128 * D_DIM);
                #pragma unroll
                for (int it = 0; it < 8; it++) {
                    int flat = it * NTHREADS + tid;
                    int r = flat >> 5, q = flat & 31;
                    CP_ASYNC16(sA + r * KS_B + q * 16, gA + r * 512 + q * 16);
                }
                CP_COMMIT();
                CP_WAIT0();
                __syncthreads();
                cur_mt = nmt;
            }
            mt = nmt; nt = nnt;
        }
    }

    grid_barrier(mygen);

    // ============ Phase 3: per-block logsumexp assembly (64 CTAs) ============
    if (blockIdx.x < NBLOCKS && tid < 128) {
        const int r = blockIdx.x;
        float tot = 0.f;
        for (int nt = r; nt < NBLOCKS; nt++) tot += g_rowpart[r][nt][tid];
        for (int m = 0; m < r; m++)          tot += g_colpart[r][m][tid];
        float v = logf(tot) - g_pos[r * 128 + tid];
        #pragma unroll
        for (int o = 16; o > 0; o >>= 1) v += __shfl_xor_sync(0xffffffffu, v, o);
        if ((tid & 31) == 0) red_r[0][tid >> 5] = v;
        __syncwarp();
    }
    __syncthreads();
    if (blockIdx.x < NBLOCKS && tid == 0) {
        g_finpart[blockIdx.x] = (red_r[0][0] + red_r[0][1]) + (red_r[0][2] + red_r[0][3]);
    }

    grid_barrier(mygen);

    // ================= Phase 4: final mean (CTA 0) =================
    if (blockIdx.x == 0 && tid < 64) {
        float s = g_finpart[tid];
        #pragma unroll
        for (int o = 16; o > 0; o >>= 1) s += __shfl_xor_sync(0xffffffffu, s, o);
        if ((tid & 31) == 0) red_c[0][tid >> 5] = s;
        __syncwarp();
        if (tid == 0) out[0] = (red_c[0][0] + red_c[0][1]) * (1.0f / (float)N_TOT);
    }
}

// ---------------------------------------------------------------------------
extern "C" void kernel_launch(void* const* d_in, const int* in_sizes, int n_in,
                              void* d_out, int out_size) {
    const float* zi = (const float*)d_in[0];
    const float* zj = (const float*)d_in[1];
    float* out = (float*)d_out;

    cudaFuncSetAttribute(ntxent_mega, cudaFuncAttributeMaxDynamicSharedMemorySize,
                         SMEM_TOTAL);

    ntxent_mega<<<GRID_MAIN, NTHREADS, SMEM_TOTAL>>>(zi, zj, out);
}